// round 1
// baseline (speedup 1.0000x reference)
#include <cuda_runtime.h>
#include <math_constants.h>

// Problem constants
#define BATCH 4
#define NTOK  2304          // 64*36
#define DIM   2048
#define VDIM  1024
#define MTOT  (BATCH * NTOK)   // 9216

// Scratch (allocation-free rule: __device__ globals)
__device__ float g_q[(size_t)BATCH * NTOK * DIM];     // 75.5 MB
__device__ float g_k[(size_t)BATCH * NTOK * DIM];     // 75.5 MB
__device__ float g_v[(size_t)BATCH * NTOK * VDIM];    // 37.7 MB
__device__ float g_adj[(size_t)BATCH * NTOK * NTOK];  // 84.9 MB

// ---------------------------------------------------------------------------
// Tiled fp32 GEMM: C = A @ B (+bias), or C = A @ B^T when TRANS_B.
//   A: [M,K] row-major (lda = K)
//   B: NN -> [K,N] row-major (ldb = N);  NT -> [N,K] row-major (ldb = K)
//   C: [M,N] row-major (ldc = N)
// Tile: 128x128x16, 256 threads, 8x8 per-thread micro-tile.
// All dims assumed divisible by 128 (M,N) and 16 (K) — true for this problem.
// ---------------------------------------------------------------------------
#define BM 128
#define BN 128
#define BK 16
#define TM 8
#define TN 8
#define LDS_PAD 4
#define LDA_S (BM + LDS_PAD)
#define LDB_S (BN + LDS_PAD)

template <bool TRANS_B, bool BIAS>
__global__ __launch_bounds__(256, 2)
void gemm128(const float* __restrict__ A,
             const float* __restrict__ B,
             const float* __restrict__ bias,
             float* __restrict__ C,
             int M, int N, int K,
             long long sAb, long long sBb, long long sCb)
{
    __shared__ float As[BK][LDA_S];
    __shared__ float Bs[BK][LDB_S];

    const float* Ab = A + (long long)blockIdx.z * sAb;
    const float* Bb = B + (long long)blockIdx.z * sBb;
    float*       Cb = C + (long long)blockIdx.z * sCb;

    const int tid  = threadIdx.x;            // 0..255
    const int row0 = blockIdx.y * BM;
    const int col0 = blockIdx.x * BN;

    const int tx = tid & 15;                 // column group
    const int ty = tid >> 4;                 // row group

    // A-tile (and NT B-tile) loader coords: float4 along K, transpose into smem
    const int ld_row = tid >> 2;             // 0..63 (then +64)
    const int ld_k4  = (tid & 3) * 4;        // 0,4,8,12
    // NN B-tile loader coords: float4 along N
    const int bn_k   = tid >> 5;             // 0..7 (then +8)
    const int bn_n4  = (tid & 31) * 4;

    float acc[TM][TN];
#pragma unroll
    for (int i = 0; i < TM; i++)
#pragma unroll
        for (int j = 0; j < TN; j++) acc[i][j] = 0.0f;

    for (int k0 = 0; k0 < K; k0 += BK) {
        // ---- load A tile (transpose K-major -> [kk][row]) ----
#pragma unroll
        for (int r = 0; r < 2; r++) {
            const int row = ld_row + r * 64;
            const float4 va = *reinterpret_cast<const float4*>(
                Ab + (long long)(row0 + row) * K + k0 + ld_k4);
            As[ld_k4 + 0][row] = va.x;
            As[ld_k4 + 1][row] = va.y;
            As[ld_k4 + 2][row] = va.z;
            As[ld_k4 + 3][row] = va.w;
        }
        // ---- load B tile ----
        if (TRANS_B) {
#pragma unroll
            for (int r = 0; r < 2; r++) {
                const int col = ld_row + r * 64;   // output column j
                const float4 vb = *reinterpret_cast<const float4*>(
                    Bb + (long long)(col0 + col) * K + k0 + ld_k4);
                Bs[ld_k4 + 0][col] = vb.x;
                Bs[ld_k4 + 1][col] = vb.y;
                Bs[ld_k4 + 2][col] = vb.z;
                Bs[ld_k4 + 3][col] = vb.w;
            }
        } else {
#pragma unroll
            for (int r = 0; r < 2; r++) {
                const int kk = bn_k + r * 8;
                const float4 vb = *reinterpret_cast<const float4*>(
                    Bb + (long long)(k0 + kk) * N + col0 + bn_n4);
                *reinterpret_cast<float4*>(&Bs[kk][bn_n4]) = vb;
            }
        }
        __syncthreads();

        // ---- compute ----
#pragma unroll
        for (int kk = 0; kk < BK; kk++) {
            float a[TM], b[TN];
#pragma unroll
            for (int i = 0; i < TM; i++) a[i] = As[kk][ty * TM + i];
#pragma unroll
            for (int j = 0; j < TN; j++) b[j] = Bs[kk][tx * TN + j];
#pragma unroll
            for (int i = 0; i < TM; i++)
#pragma unroll
                for (int j = 0; j < TN; j++)
                    acc[i][j] = fmaf(a[i], b[j], acc[i][j]);
        }
        __syncthreads();
    }

    // ---- epilogue ----
#pragma unroll
    for (int i = 0; i < TM; i++) {
        const long long row = row0 + ty * TM + i;
#pragma unroll
        for (int j = 0; j < TN; j += 4) {
            float4 v;
            v.x = acc[i][j + 0];
            v.y = acc[i][j + 1];
            v.z = acc[i][j + 2];
            v.w = acc[i][j + 3];
            if (BIAS) {
                const int c = col0 + tx * TN + j;
                v.x += bias[c + 0];
                v.y += bias[c + 1];
                v.z += bias[c + 2];
                v.w += bias[c + 3];
            }
            *reinterpret_cast<float4*>(Cb + row * N + col0 + tx * TN + j) = v;
        }
    }
}

// ---------------------------------------------------------------------------
// Row softmax over 2304 elements: one CTA (256 threads) per row, 9 values
// register-resident per thread -> single read + single write of adj.
// ---------------------------------------------------------------------------
__global__ __launch_bounds__(256)
void softmax2304(float* __restrict__ adj)
{
    float* p = adj + (long long)blockIdx.x * NTOK;
    const int t = threadIdx.x;
    __shared__ float red[256];

    float v[9];
    float m = -CUDART_INF_F;
#pragma unroll
    for (int i = 0; i < 9; i++) {
        v[i] = p[t + i * 256];
        m = fmaxf(m, v[i]);
    }
    red[t] = m;
    __syncthreads();
#pragma unroll
    for (int s = 128; s > 0; s >>= 1) {
        if (t < s) red[t] = fmaxf(red[t], red[t + s]);
        __syncthreads();
    }
    m = red[0];
    __syncthreads();

    float sum = 0.0f;
#pragma unroll
    for (int i = 0; i < 9; i++) {
        v[i] = __expf(v[i] - m);
        sum += v[i];
    }
    red[t] = sum;
    __syncthreads();
#pragma unroll
    for (int s = 128; s > 0; s >>= 1) {
        if (t < s) red[t] += red[t + s];
        __syncthreads();
    }
    const float inv = 1.0f / red[0];
#pragma unroll
    for (int i = 0; i < 9; i++) p[t + i * 256] = v[i] * inv;
}

// ---------------------------------------------------------------------------
extern "C" void kernel_launch(void* const* d_in, const int* in_sizes, int n_in,
                              void* d_out, int out_size)
{
    const float* feats = (const float*)d_in[0];
    const float* Wq    = (const float*)d_in[1];
    const float* bq    = (const float*)d_in[2];
    const float* Wk    = (const float*)d_in[3];
    const float* bk    = (const float*)d_in[4];
    const float* Wu    = (const float*)d_in[5];
    const float* bu    = (const float*)d_in[6];
    float*       out   = (float*)d_out;

    float *qp, *kp, *vp, *adjp;
    cudaGetSymbolAddress((void**)&qp,   g_q);
    cudaGetSymbolAddress((void**)&kp,   g_k);
    cudaGetSymbolAddress((void**)&vp,   g_v);
    cudaGetSymbolAddress((void**)&adjp, g_adj);

    const dim3 blk(256);

    // q = feats @ Wq + bq   [9216, 2048]
    gemm128<false, true><<<dim3(DIM / BN, MTOT / BM, 1), blk>>>(
        feats, Wq, bq, qp, MTOT, DIM, DIM, 0, 0, 0);
    // k = feats @ Wk + bk
    gemm128<false, true><<<dim3(DIM / BN, MTOT / BM, 1), blk>>>(
        feats, Wk, bk, kp, MTOT, DIM, DIM, 0, 0, 0);
    // v = feats @ Wu + bu   [9216, 1024]
    gemm128<false, true><<<dim3(VDIM / BN, MTOT / BM, 1), blk>>>(
        feats, Wu, bu, vp, MTOT, VDIM, DIM, 0, 0, 0);

    // adj[b] = q[b] @ k[b]^T   [2304, 2304] per batch
    gemm128<true, false><<<dim3(NTOK / BN, NTOK / BM, BATCH), blk>>>(
        qp, kp, nullptr, adjp, NTOK, NTOK, DIM,
        (long long)NTOK * DIM, (long long)NTOK * DIM, (long long)NTOK * NTOK);

    // row softmax
    softmax2304<<<MTOT, blk>>>(adjp);

    // out[b] = adj[b] @ v[b]   [2304, 1024] per batch
    gemm128<false, false><<<dim3(VDIM / BN, NTOK / BM, BATCH), blk>>>(
        adjp, vp, nullptr, out, NTOK, VDIM, NTOK,
        (long long)NTOK * NTOK, (long long)NTOK * VDIM, (long long)NTOK * VDIM);
}